// round 2
// baseline (speedup 1.0000x reference)
#include <cuda_runtime.h>
#include <math.h>

#define BB 64
#define TT 101
#define TS 100
#define VV 8000
#define HH 512
#define GG 2048
#define MM (TS*BB)   // 6400
#define EPSN 1e-5f

// ---------------- device scratch (static; no runtime allocation) -------------
__device__ float g_e[MM*HH];                     // [m][h] embedded inputs, m = t*64+b
__device__ float g_Xg1[(size_t)GG*MM];           // [n][m] precomputed e@Wih1^T + b1 (transposed)
__device__ float g_Hout[MM*HH];                  // [m][h] layer-3 bn*mask output per step
__device__ float g_logits[(size_t)MM*VV];        // [m][v]
__device__ float g_part[8*GG*BB];                // [slot][n][b] split-K partials
__device__ float g_h[3*BB*HH];
__device__ float g_c[3*BB*HH];
__device__ float g_hd[2*BB*HH];

// ---------------- init: zero states + loss slot ------------------------------
__global__ void k_init(float* out, int hasLoss) {
    int i = blockIdx.x * blockDim.x + threadIdx.x;
    if (i < 3*BB*HH) { g_h[i] = 0.f; g_c[i] = 0.f; }
    if (i == 0 && hasLoss) out[0] = 0.f;
}

// ---------------- embedding gather: g_e[(t*64+b)*512+h] = emb[x[b,t]][h] -----
__global__ void k_embed(const int* x, const float* emb) {
    int i = blockIdx.x * blockDim.x + threadIdx.x;
    if (i >= MM * (HH/4)) return;
    int m  = i / (HH/4);
    int hq = i % (HH/4);
    int t = m / BB, b = m % BB;
    int tok = x[b*TT + t];
    ((float4*)g_e)[(size_t)m*(HH/4) + hq] =
        ((const float4*)emb)[(size_t)tok*(HH/4) + hq];
}

// ---------------- big SGEMM: 128x128 tile, 8x8/thread, K=512 ----------------
// MODE 0: C=g_Xg1 (transposed [n][m]) = g_e @ Bw^T + bias, N=2048
// MODE 1: C=g_logits [m][v]           = g_Hout @ Bw^T + bias, N=8000
template<int MODE>
__global__ void k_gemm_big(const float* __restrict__ Bw, const float* __restrict__ bias) {
    const int N = (MODE == 0) ? GG : VV;
    const float* A = (MODE == 0) ? g_e : g_Hout;
    __shared__ __align__(16) float Ast[16][132];
    __shared__ __align__(16) float Bst[16][132];
    int tid = threadIdx.x;
    int mBase = blockIdx.y * 128, nBase = blockIdx.x * 128;
    int lr = tid >> 2, lc = (tid & 3) * 4;       // rows lr and lr+64, 4 float4 cols
    int m0 = (tid >> 4) * 8, n0 = (tid & 15) * 8;
    float acc[8][8];
#pragma unroll
    for (int i = 0; i < 8; i++)
#pragma unroll
        for (int j = 0; j < 8; j++) acc[i][j] = 0.f;

    for (int kb = 0; kb < 512; kb += 16) {
        // each thread loads TWO float4 per tile (rows lr, lr+64): full 128x16
        float4 av0 = *(const float4*)&A[(size_t)(mBase + lr)*512 + kb + lc];
        float4 av1 = *(const float4*)&A[(size_t)(mBase + lr + 64)*512 + kb + lc];
        int ng0 = nBase + lr, ng1 = nBase + lr + 64;
        float4 bv0 = make_float4(0.f,0.f,0.f,0.f), bv1 = make_float4(0.f,0.f,0.f,0.f);
        if (ng0 < N) bv0 = *(const float4*)&Bw[(size_t)ng0*512 + kb + lc];
        if (ng1 < N) bv1 = *(const float4*)&Bw[(size_t)ng1*512 + kb + lc];
        __syncthreads();
        Ast[lc+0][lr] = av0.x; Ast[lc+1][lr] = av0.y; Ast[lc+2][lr] = av0.z; Ast[lc+3][lr] = av0.w;
        Ast[lc+0][lr+64] = av1.x; Ast[lc+1][lr+64] = av1.y; Ast[lc+2][lr+64] = av1.z; Ast[lc+3][lr+64] = av1.w;
        Bst[lc+0][lr] = bv0.x; Bst[lc+1][lr] = bv0.y; Bst[lc+2][lr] = bv0.z; Bst[lc+3][lr] = bv0.w;
        Bst[lc+0][lr+64] = bv1.x; Bst[lc+1][lr+64] = bv1.y; Bst[lc+2][lr+64] = bv1.z; Bst[lc+3][lr+64] = bv1.w;
        __syncthreads();
#pragma unroll
        for (int kk = 0; kk < 16; kk++) {
            float a[8], b[8];
            *(float4*)&a[0] = *(float4*)&Ast[kk][m0];
            *(float4*)&a[4] = *(float4*)&Ast[kk][m0+4];
            *(float4*)&b[0] = *(float4*)&Bst[kk][n0];
            *(float4*)&b[4] = *(float4*)&Bst[kk][n0+4];
#pragma unroll
            for (int i = 0; i < 8; i++)
#pragma unroll
                for (int j = 0; j < 8; j++) acc[i][j] += a[i] * b[j];
        }
    }

    if (MODE == 0) {
#pragma unroll
        for (int j = 0; j < 8; j++) {
            int n = nBase + n0 + j;
            float bb = bias[n];
#pragma unroll
            for (int i = 0; i < 8; i++)
                g_Xg1[(size_t)n*MM + mBase + m0 + i] = acc[i][j] + bb;
        }
    } else {
#pragma unroll
        for (int i = 0; i < 8; i++) {
            int m = mBase + m0 + i;
#pragma unroll
            for (int j = 0; j < 8; j++) {
                int n = nBase + n0 + j;
                if (n < VV) g_logits[(size_t)m*VV + n] = acc[i][j] + bias[n];
            }
        }
    }
}

// ---------------- per-step GEMM: 64x64 tile, 4x4/thread, split-K=128 --------
// layer 0: chunks 0..3 = g_h(l0) @ W0(Whh1)
// layer>0: chunks 0..3 = g_hd(l-1) @ W0(Wih), chunks 4..7 = g_h(l) @ W1(Whh)
// writes g_part[chunk][(n)*64 + b]
__global__ void k_gemm_step(int layer, const float* __restrict__ W0,
                            const float* __restrict__ W1) {
    int chunk = blockIdx.y;
    const float* A; const float* Bw; int kOff;
    if (layer == 0) { A = g_h; Bw = W0; kOff = chunk * 128; }
    else if (chunk < 4) { A = g_hd + (layer-1)*BB*HH; Bw = W0; kOff = chunk * 128; }
    else { A = g_h + layer*BB*HH; Bw = W1; kOff = (chunk-4) * 128; }

    int nBase = blockIdx.x * 64;
    __shared__ __align__(16) float Ast[32][68];
    __shared__ __align__(16) float Bst[32][68];
    int tid = threadIdx.x;
    int lr = tid >> 3, lc = (tid & 7) * 4;       // rows lr and lr+32, 8 float4 cols
    int m0 = (tid >> 4) * 4, n0 = (tid & 15) * 4;
    float acc[4][4];
#pragma unroll
    for (int i = 0; i < 4; i++)
#pragma unroll
        for (int j = 0; j < 4; j++) acc[i][j] = 0.f;

    for (int kb = 0; kb < 128; kb += 32) {
        // TWO float4 loads per operand (rows lr, lr+32): full 64x32 tile
        float4 av0 = *(const float4*)&A[(size_t)lr*512 + kOff + kb + lc];
        float4 av1 = *(const float4*)&A[(size_t)(lr+32)*512 + kOff + kb + lc];
        float4 bv0 = *(const float4*)&Bw[(size_t)(nBase + lr)*512 + kOff + kb + lc];
        float4 bv1 = *(const float4*)&Bw[(size_t)(nBase + lr + 32)*512 + kOff + kb + lc];
        __syncthreads();
        Ast[lc+0][lr] = av0.x; Ast[lc+1][lr] = av0.y; Ast[lc+2][lr] = av0.z; Ast[lc+3][lr] = av0.w;
        Ast[lc+0][lr+32] = av1.x; Ast[lc+1][lr+32] = av1.y; Ast[lc+2][lr+32] = av1.z; Ast[lc+3][lr+32] = av1.w;
        Bst[lc+0][lr] = bv0.x; Bst[lc+1][lr] = bv0.y; Bst[lc+2][lr] = bv0.z; Bst[lc+3][lr] = bv0.w;
        Bst[lc+0][lr+32] = bv1.x; Bst[lc+1][lr+32] = bv1.y; Bst[lc+2][lr+32] = bv1.z; Bst[lc+3][lr+32] = bv1.w;
        __syncthreads();
#pragma unroll
        for (int kk = 0; kk < 32; kk++) {
            float a[4], b[4];
            *(float4*)&a[0] = *(float4*)&Ast[kk][m0];
            *(float4*)&b[0] = *(float4*)&Bst[kk][n0];
#pragma unroll
            for (int i = 0; i < 4; i++)
#pragma unroll
                for (int j = 0; j < 4; j++) acc[i][j] += a[i] * b[j];
        }
    }
    float* P = g_part + (size_t)chunk*GG*BB;
#pragma unroll
    for (int j = 0; j < 4; j++)
#pragma unroll
        for (int i = 0; i < 4; i++)
            P[(size_t)(nBase + n0 + j)*BB + m0 + i] = acc[i][j];
}

// ---------------- LSTM cell + BatchNorm(train) + locked dropout -------------
// grid = 512 (feature j), block = 64 (batch b)
__global__ void k_lstm_bn(int layer, int t, int nslots,
                          const float* __restrict__ bias,
                          const float* __restrict__ gamma,
                          const float* __restrict__ beta,
                          const float* __restrict__ mask) {
    int j = blockIdx.x;
    int b = threadIdx.x;
    float gate[4];
#pragma unroll
    for (int g = 0; g < 4; g++) {
        int n = g*HH + j;
        float s = bias ? bias[n] : 0.f;
        if (layer == 0) s += g_Xg1[(size_t)n*MM + t*BB + b];
        for (int sl = 0; sl < nslots; sl++)
            s += g_part[(size_t)sl*GG*BB + (size_t)n*BB + b];
        gate[g] = s;
    }
    float* hP = g_h + layer*BB*HH;
    float* cP = g_c + layer*BB*HH;
    float iv = 1.f / (1.f + expf(-gate[0]));
    float fv = 1.f / (1.f + expf(-gate[1]));
    float gv = tanhf(gate[2]);
    float ov = 1.f / (1.f + expf(-gate[3]));
    float cc = fv * cP[b*HH + j] + iv * gv;
    float hh = ov * tanhf(cc);
    cP[b*HH + j] = cc;
    hP[b*HH + j] = hh;

    // BatchNorm over batch dimension (64 threads in this block)
    float sum = hh, sq = hh * hh;
#pragma unroll
    for (int o = 16; o; o >>= 1) {
        sum += __shfl_down_sync(0xffffffffu, sum, o);
        sq  += __shfl_down_sync(0xffffffffu, sq,  o);
    }
    __shared__ float s0[2], s1[2];
    int warp = b >> 5, lane = b & 31;
    if (lane == 0) { s0[warp] = sum; s1[warp] = sq; }
    __syncthreads();
    float mu  = (s0[0] + s0[1]) * (1.f / BB);
    float var = (s1[0] + s1[1]) * (1.f / BB) - mu * mu;
    float hd = (gamma[j] * (hh - mu) * rsqrtf(var + EPSN) + beta[j]) * mask[b*HH + j];
    float* outP = (layer == 2) ? (g_Hout + (size_t)t*BB*HH) : (g_hd + layer*BB*HH);
    outP[b*HH + j] = hd;
}

// ---------------- loss: mean NLL over 6400 rows of 8000 logits --------------
__global__ void k_loss(const int* __restrict__ x, float* out) {
    int r = blockIdx.x;            // r = t*64 + b
    int t = r >> 6, b = r & 63;
    const float* row = &g_logits[(size_t)r * VV];
    int tid = threadIdx.x;
    float m = -INFINITY, s = 0.f;
    for (int v = tid; v < VV; v += 256) {
        float xv = row[v];
        if (xv > m) { s = s * expf(m - xv) + 1.f; m = xv; }
        else s += expf(xv - m);
    }
    __shared__ float sm[256], ss[256];
    sm[tid] = m; ss[tid] = s;
    __syncthreads();
    for (int o = 128; o; o >>= 1) {
        if (tid < o) {
            float m2 = sm[tid + o], s2 = ss[tid + o];
            float mm = fmaxf(sm[tid], m2);
            ss[tid] = ss[tid] * expf(sm[tid] - mm) + s2 * expf(m2 - mm);
            sm[tid] = mm;
        }
        __syncthreads();
    }
    if (tid == 0) {
        int tgt = x[b*TT + t + 1];
        float lse = sm[0] + logf(ss[0]);
        atomicAdd(out, (lse - row[tgt]) * (1.f / MM));
    }
}

// ---------------- transpose [t*64+b][v] -> out[b][v][t] ---------------------
__global__ void k_transpose(float* __restrict__ outLogits) {
    int b = blockIdx.x;
    int v0 = blockIdx.y * 32;
    __shared__ float tile[32 * 101];
    int tid = threadIdx.x;
    for (int idx = tid; idx < 3200; idx += 256) {
        int t = idx >> 5, vi = idx & 31;
        tile[vi*101 + t] = g_logits[(size_t)(t*BB + b)*VV + v0 + vi];
    }
    __syncthreads();
    for (int idx = tid; idx < 3200; idx += 256) {
        int vi = idx / 100, t = idx - vi*100;
        outLogits[(size_t)b*VV*TS + (size_t)(v0 + vi)*TS + t] = tile[vi*101 + t];
    }
}

// ---------------- launch ------------------------------------------------------
extern "C" void kernel_launch(void* const* d_in, const int* in_sizes, int n_in,
                              void* d_out, int out_size) {
    const int*   x   = (const int*)d_in[0];
    const float* emb = (const float*)d_in[1];
    const float* Wd  = (const float*)d_in[2];
    const float* bd  = (const float*)d_in[3];
    const float* Wih[3] = {(const float*)d_in[4],  (const float*)d_in[10], (const float*)d_in[16]};
    const float* Whh[3] = {(const float*)d_in[5],  (const float*)d_in[11], (const float*)d_in[17]};
    const float* bl[3]  = {(const float*)d_in[6],  (const float*)d_in[12], (const float*)d_in[18]};
    const float* gm[3]  = {(const float*)d_in[7],  (const float*)d_in[13], (const float*)d_in[19]};
    const float* bt[3]  = {(const float*)d_in[8],  (const float*)d_in[14], (const float*)d_in[20]};
    const float* mk[3]  = {(const float*)d_in[9],  (const float*)d_in[15], (const float*)d_in[21]};

    float* out = (float*)d_out;
    // out_size is 1 + B*V*(T-1) when loss is packed first (51,200,001 odd).
    int hasLoss = (out_size & 1) ? 1 : 0;
    float* outLogits = out + hasLoss;

    k_init<<<(3*BB*HH + 255)/256, 256>>>(out, hasLoss);
    k_embed<<<(MM*(HH/4) + 255)/256, 256>>>(x, emb);
    k_gemm_big<0><<<dim3(GG/128, MM/128), 256>>>(Wih[0], bl[0]);

    for (int t = 0; t < TS; t++) {
        k_gemm_step<<<dim3(GG/64, 4), 256>>>(0, Whh[0], nullptr);
        k_lstm_bn<<<HH, BB>>>(0, t, 4, nullptr, gm[0], bt[0], mk[0]);
        k_gemm_step<<<dim3(GG/64, 8), 256>>>(1, Wih[1], Whh[1]);
        k_lstm_bn<<<HH, BB>>>(1, t, 8, bl[1], gm[1], bt[1], mk[1]);
        k_gemm_step<<<dim3(GG/64, 8), 256>>>(2, Wih[2], Whh[2]);
        k_lstm_bn<<<HH, BB>>>(2, t, 8, bl[2], gm[2], bt[2], mk[2]);
    }

    k_gemm_big<1><<<dim3((VV + 127)/128, MM/128), 256>>>(Wd, bd);
    if (hasLoss) k_loss<<<MM, 256>>>(x, out);
    k_transpose<<<dim3(BB, VV/32), 256>>>(outLogits);
}